// round 3
// baseline (speedup 1.0000x reference)
#include <cuda_runtime.h>
#include <math.h>

#define NA 20000
#define NE 640000
#define DD 128
#define GG 32
#define HH 8
#define NIT 4
#define NSM 148

// ---------------- device scratch ----------------
__device__ float    g_Wfil[(size_t)NE * DD];
__device__ int      g_ssrc[NE];     // src, sorted by dst
__device__ int      g_sdst[NE];     // dst, sorted (nondecreasing)
__device__ int      g_lsrc[NE];     // live subset, sorted by dst
__device__ int      g_ldst[NE];
__device__ int      g_lpos[NE];     // live -> sorted-edge position (for g_s)
__device__ int      g_cnt_all[NA];
__device__ int      g_cnt_live[NA];
__device__ int      g_off_all[NA];
__device__ int      g_off_live[NA];
__device__ int      g_nlive;
__device__ float    g_h[NA * DD];
__device__ float    g_Q[NA * DD];
__device__ float    g_K[NA * DD];
__device__ float    g_s[NE * HH];
__device__ unsigned g_smax[NA * HH];
__device__ float    g_den[NA * HH];
__device__ float    g_msg[NA * DD];

__device__ __forceinline__ unsigned fenc(float f) {
    unsigned u = __float_as_uint(f);
    return (u & 0x80000000u) ? ~u : (u | 0x80000000u);
}
__device__ __forceinline__ float fdec(unsigned u) {
    return __uint_as_float((u & 0x80000000u) ? (u & 0x7fffffffu) : ~u);
}
__device__ __forceinline__ void red_add_v4(float* p, float x, float y, float z, float w) {
    asm volatile("red.global.add.v4.f32 [%0], {%1,%2,%3,%4};"
                 :: "l"(p), "f"(x), "f"(y), "f"(z), "f"(w) : "memory");
}
__device__ __forceinline__ float edge_r(const float* xyz, int s, int d) {
    float dx = xyz[3 * s]     - xyz[3 * d];
    float dy = xyz[3 * s + 1] - xyz[3 * d + 1];
    float dz = xyz[3 * s + 2] - xyz[3 * d + 2];
    return sqrtf(dx * dx + dy * dy + dz * dz + 1e-12f);
}

// ---------------- GEMM core: k-chunk 4, float4 loads ----------------
#define ROW8(i) (((i) < 4) ? (4 * ty + (i)) : (64 + 4 * ty + ((i) - 4)))

template <int K, int LDA>
__device__ __forceinline__ void gemm8x8(const float* __restrict__ A,
                                        const float* __restrict__ B,
                                        int tx, int ty, float acc[8][8]) {
#pragma unroll 2
    for (int kk = 0; kk < K; kk += 4) {
        float av[8][4], bv[4][8];
#pragma unroll
        for (int i = 0; i < 4; i++) {
            *(float4*)av[i]   = *(const float4*)(A + (4 * ty + i) * LDA + kk);
            *(float4*)av[4+i] = *(const float4*)(A + (64 + 4 * ty + i) * LDA + kk);
        }
#pragma unroll
        for (int q = 0; q < 4; q++) {
            *(float4*)(&bv[q][0]) = *(const float4*)(B + (kk + q) * 128 + 4 * tx);
            *(float4*)(&bv[q][4]) = *(const float4*)(B + (kk + q) * 128 + 64 + 4 * tx);
        }
#pragma unroll
        for (int q = 0; q < 4; q++)
#pragma unroll
            for (int i = 0; i < 8; i++)
#pragma unroll
                for (int j = 0; j < 8; j++)
                    acc[i][j] = fmaf(av[i][q], bv[q][j], acc[i][j]);
    }
}
__device__ __forceinline__ void zero8x8(float acc[8][8]) {
#pragma unroll
    for (int i = 0; i < 8; i++)
#pragma unroll
        for (int j = 0; j < 8; j++) acc[i][j] = 0.f;
}

// ---------------- setup: embed + zero counters ----------------
__global__ void k_embed(const float* __restrict__ emb, const int* __restrict__ z,
                        float* __restrict__ x) {
    int i = blockIdx.x * blockDim.x + threadIdx.x;
    if (i < NA) { g_cnt_all[i] = 0; g_cnt_live[i] = 0; }
    if (i < NA * DD) {
        int n = i >> 7, d = i & 127;
        x[i] = emb[z[n] * DD + d];
    }
}

// histogram of dst (all + live)
__global__ void k_hist(const float* __restrict__ xyz, const int* __restrict__ src,
                       const int* __restrict__ dst) {
    int e = blockIdx.x * blockDim.x + threadIdx.x;
    if (e >= NE) return;
    int s = src[e], d = dst[e];
    atomicAdd(&g_cnt_all[d], 1);
    if (edge_r(xyz, s, d) < 8.f) atomicAdd(&g_cnt_live[d], 1);
}

// single-block exclusive scan over both histograms; zero counters; set g_nlive
__global__ __launch_bounds__(512) void k_scan() {
    __shared__ int part[512];
    __shared__ int total;
    int t = threadIdx.x;
    const int CH = (NA + 511) / 512;   // 40
#pragma unroll 1
    for (int pass = 0; pass < 2; pass++) {
        int* cnt = pass ? g_cnt_live : g_cnt_all;
        int* off = pass ? g_off_live : g_off_all;
        int lo = t * CH, hi = min(lo + CH, NA);
        int s = 0;
        for (int i = lo; i < hi; i++) s += cnt[i];
        part[t] = s;
        __syncthreads();
        if (t == 0) {
            int run = 0;
            for (int i = 0; i < 512; i++) { int v = part[i]; part[i] = run; run += v; }
            total = run;
        }
        __syncthreads();
        int run = part[t];
        for (int i = lo; i < hi; i++) { int v = cnt[i]; off[i] = run; run += v; cnt[i] = 0; }
        if (pass == 1 && t == 0) g_nlive = total;
        __syncthreads();
    }
}

// scatter edges into dst-sorted order; compact live subset (also dst-sorted)
__global__ void k_scatter(const float* __restrict__ xyz, const int* __restrict__ src,
                          const int* __restrict__ dst) {
    int e = blockIdx.x * blockDim.x + threadIdx.x;
    if (e >= NE) return;
    int s = src[e], d = dst[e];
    int pos = g_off_all[d] + atomicAdd(&g_cnt_all[d], 1);
    g_ssrc[pos] = s;
    g_sdst[pos] = d;
    if (edge_r(xyz, s, d) < 8.f) {
        int lp = g_off_live[d] + atomicAdd(&g_cnt_live[d], 1);
        g_lsrc[lp] = s; g_ldst[lp] = d; g_lpos[lp] = pos;
    }
}

// persistent filter over live edges
__global__ __launch_bounds__(256) void k_filter(
    const float* __restrict__ xyz,
    const float* __restrict__ Wl, const float* __restrict__ bl,
    const float* __restrict__ W1f, const float* __restrict__ b1f,
    const float* __restrict__ W2f, const float* __restrict__ b2f) {
    extern __shared__ float sm[];
    float* sf  = sm;                   // 128*36
    float* sg  = sf + 128 * 36;        // 128*132
    float* sW1 = sg + 128 * 132;
    float* sWl = sW1 + 32 * 128;
    float* sW2 = sWl + 32 * 128;
    float* sr  = sW2 + 128 * 128;
    float* sC  = sr + 128;
    float* sb1 = sC + 128;
    float* sb  = sb1 + 128;

    int tid = threadIdx.x, tx = tid & 15, ty = tid >> 4;

    for (int i = tid; i < 32 * 128; i += 256) { sW1[i] = W1f[i]; sWl[i] = Wl[i]; }
    for (int i = tid; i < 128 * 128; i += 256) sW2[i] = W2f[i];
    if (tid < 128) { sb1[tid] = b1f[tid]; sb[tid] = bl[tid] + b2f[tid]; }

    int nlive = g_nlive;
    for (int t = blockIdx.x; t * 128 < nlive; t += gridDim.x) {
        if (tid < 128) {
            int li = t * 128 + tid;
            float r = 100.f, C = 0.f;
            if (li < nlive) {
                r = edge_r(xyz, g_lsrc[li], g_ldst[li]);
                C = (r < 8.f) ? (0.5f * (cospif(r * 0.125f) + 1.f)) : 0.f;
            }
            sr[tid] = r; sC[tid] = C;
        }
        __syncthreads();
        {
            int el = tid >> 1, kb = (tid & 1) * 16;
            float r = sr[el];
#pragma unroll
            for (int q = 0; q < 16; q++) {
                float off = (float)(kb + q) * (8.f / 31.f);
                float u = (r - off) * (31.f / 8.f);
                sf[el * 36 + kb + q] = __expf(-0.5f * u * u);
            }
        }
        __syncthreads();

        float acc[8][8];
        zero8x8(acc);
        gemm8x8<32, 36>(sf, sW1, tx, ty, acc);
#pragma unroll
        for (int i = 0; i < 8; i++) {
            int r = ROW8(i);
#pragma unroll
            for (int j = 0; j < 8; j++) {
                int c = (j < 4) ? (4 * tx + j) : (64 + 4 * tx + j - 4);
                float v = acc[i][j] + sb1[c];
                sg[r * 132 + c] = v / (1.f + __expf(-v));
            }
        }
        __syncthreads();

        zero8x8(acc);
        gemm8x8<32, 36>(sf, sWl, tx, ty, acc);
        gemm8x8<128, 132>(sg, sW2, tx, ty, acc);
#pragma unroll
        for (int i = 0; i < 8; i++) {
            int r = ROW8(i);
            int li = t * 128 + r;
            if (li < nlive) {
                float Cv = sC[r];
                float* out = g_Wfil + (size_t)li * 128;
#pragma unroll
                for (int j = 0; j < 8; j++) {
                    int c = (j < 4) ? (4 * tx + j) : (64 + 4 * tx + j - 4);
                    out[c] = (acc[i][j] + sb[c]) * Cv;
                }
            }
        }
        __syncthreads();
    }
}

// h = x + te; Q = h@Wq; K = h@Wk
__global__ __launch_bounds__(256) void k_hqk(const float* __restrict__ x,
                                             const float* __restrict__ te,
                                             const float* __restrict__ Wq,
                                             const float* __restrict__ Wk, int it) {
    extern __shared__ float sm[];
    float* sh = sm;               // 128*132
    float* sB = sh + 128 * 132;   // 128*128
    int tid = threadIdx.x, tx = tid & 15, ty = tid >> 4;
    int n0 = blockIdx.x * 128;

    for (int i = tid; i < 128 * 128; i += 256) {
        int r = i >> 7, c = i & 127;
        int n = n0 + r;
        float v = 0.f;
        if (n < NA) {
            v = x[n * 128 + c] + te[it * 128 + c];
            g_h[n * 128 + c] = v;
        }
        sh[r * 132 + c] = v;
    }
    for (int i = tid; i < 128 * 128; i += 256) sB[i] = Wq[i];
    __syncthreads();

    float acc[8][8];
    zero8x8(acc);
    gemm8x8<128, 132>(sh, sB, tx, ty, acc);
#pragma unroll
    for (int i = 0; i < 8; i++) {
        int n = n0 + ROW8(i);
        if (n < NA) {
            *(float4*)(g_Q + n * 128 + 4 * tx)      = make_float4(acc[i][0], acc[i][1], acc[i][2], acc[i][3]);
            *(float4*)(g_Q + n * 128 + 64 + 4 * tx) = make_float4(acc[i][4], acc[i][5], acc[i][6], acc[i][7]);
        }
    }
    __syncthreads();
    for (int i = tid; i < 128 * 128; i += 256) sB[i] = Wk[i];
    __syncthreads();
    zero8x8(acc);
    gemm8x8<128, 132>(sh, sB, tx, ty, acc);
#pragma unroll
    for (int i = 0; i < 8; i++) {
        int n = n0 + ROW8(i);
        if (n < NA) {
            *(float4*)(g_K + n * 128 + 4 * tx)      = make_float4(acc[i][0], acc[i][1], acc[i][2], acc[i][3]);
            *(float4*)(g_K + n * 128 + 64 + 4 * tx) = make_float4(acc[i][4], acc[i][5], acc[i][6], acc[i][7]);
        }
    }
}

// scores + segment max over sorted edges; one warp per edge
__global__ void k_s() {
    int w = (blockIdx.x * blockDim.x + threadIdx.x) >> 5;
    int lane = threadIdx.x & 31;
    if (w >= NE) return;
    int s = g_ssrc[w], d = g_sdst[w];
    float4 q = *(const float4*)(g_Q + d * 128 + lane * 4);
    float4 k = *(const float4*)(g_K + s * 128 + lane * 4);
    float p = q.x * k.x + q.y * k.y + q.z * k.z + q.w * k.w;
    p += __shfl_xor_sync(0xffffffffu, p, 1);
    p += __shfl_xor_sync(0xffffffffu, p, 2);
    if ((lane & 3) == 0) {
        int h = lane >> 2;
        float sv = p * 0.25f;
        g_s[w * 8 + h] = sv;
        atomicMax(&g_smax[d * 8 + h], fenc(sv));
    }
}

// es = exp(s - max); warp-segmented denom reduction (dst sorted => monotone)
__global__ void k_es() {
    int e = blockIdx.x * blockDim.x + threadIdx.x;   // NE divisible by 256
    int lane = threadIdx.x & 31;
    int d = g_sdst[e];
    uint4 m0 = *(const uint4*)(g_smax + d * 8);
    uint4 m1 = *(const uint4*)(g_smax + d * 8 + 4);
    float4 s0 = *(const float4*)(g_s + e * 8);
    float4 s1 = *(const float4*)(g_s + e * 8 + 4);
    float v[8];
    v[0] = __expf(s0.x - fdec(m0.x)); v[1] = __expf(s0.y - fdec(m0.y));
    v[2] = __expf(s0.z - fdec(m0.z)); v[3] = __expf(s0.w - fdec(m0.w));
    v[4] = __expf(s1.x - fdec(m1.x)); v[5] = __expf(s1.y - fdec(m1.y));
    v[6] = __expf(s1.z - fdec(m1.z)); v[7] = __expf(s1.w - fdec(m1.w));
    *(float4*)(g_s + e * 8)     = make_float4(v[0], v[1], v[2], v[3]);
    *(float4*)(g_s + e * 8 + 4) = make_float4(v[4], v[5], v[6], v[7]);
    // segmented suffix-sum within warp (segments contiguous since sorted)
#pragma unroll
    for (int delta = 1; delta < 32; delta <<= 1) {
        int od = __shfl_down_sync(0xffffffffu, d, delta);
        float ov[8];
#pragma unroll
        for (int q = 0; q < 8; q++) ov[q] = __shfl_down_sync(0xffffffffu, v[q], delta);
        if (lane + delta < 32 && od == d)
#pragma unroll
            for (int q = 0; q < 8; q++) v[q] += ov[q];
    }
    int pd = __shfl_up_sync(0xffffffffu, d, 1);
    if (lane == 0 || pd != d) {
        red_add_v4(g_den + d * 8,     v[0], v[1], v[2], v[3]);
        red_add_v4(g_den + d * 8 + 4, v[4], v[5], v[6], v[7]);
    }
}

__global__ void k_recip() {
    int i = blockIdx.x * blockDim.x + threadIdx.x;
    if (i < NA * HH) g_den[i] = 1.f / (g_den[i] + 1e-12f);
}

// persistent fused msg: A = h[src] ⊙ Wfil ; v = A @ Wv ; segmented-reduce ; red per segment
__global__ __launch_bounds__(256) void k_msgv(const float* __restrict__ Wv) {
    extern __shared__ float sm[];
    float* sA  = sm;                   // 128*132
    float* sB  = sA + 128 * 132;       // 128*128
    float* sAf = sB + 128 * 128;       // 128*8
    int*   sDst = (int*)(sAf + 128 * 8);
    int tid = threadIdx.x, tx = tid & 15, ty = tid >> 4;

    for (int i = tid; i < 128 * 128; i += 256) sB[i] = Wv[i];
    int nlive = g_nlive;

    for (int t = blockIdx.x; t * 128 < nlive; t += gridDim.x) {
        if (tid < 128) {
            int li = t * 128 + tid;
            if (li < nlive) {
                int d = g_ldst[li];
                int pos = g_lpos[li];
                sDst[tid] = d;
                float4 s0 = *(const float4*)(g_s + (size_t)pos * 8);
                float4 s1 = *(const float4*)(g_s + (size_t)pos * 8 + 4);
                float4 d0 = *(const float4*)(g_den + d * 8);
                float4 d1 = *(const float4*)(g_den + d * 8 + 4);
                *(float4*)(sAf + tid * 8)     = make_float4(s0.x * d0.x, s0.y * d0.y, s0.z * d0.z, s0.w * d0.w);
                *(float4*)(sAf + tid * 8 + 4) = make_float4(s1.x * d1.x, s1.y * d1.y, s1.z * d1.z, s1.w * d1.w);
            } else sDst[tid] = -1;
        }
        {
            int r = tid >> 1, cb = (tid & 1) * 64;
            int li = t * 128 + r;
            if (li < nlive) {
                int s = g_lsrc[li];
                const float4* wf = (const float4*)(g_Wfil + (size_t)li * 128 + cb);
                const float4* hp = (const float4*)(g_h + (size_t)s * 128 + cb);
#pragma unroll
                for (int q = 0; q < 16; q++) {
                    float4 w = wf[q], hh = hp[q];
                    *(float4*)(sA + r * 132 + cb + q * 4) =
                        make_float4(w.x * hh.x, w.y * hh.y, w.z * hh.z, w.w * hh.w);
                }
            } else {
#pragma unroll
                for (int q = 0; q < 16; q++)
                    *(float4*)(sA + r * 132 + cb + q * 4) = make_float4(0.f, 0.f, 0.f, 0.f);
            }
        }
        __syncthreads();

        float acc[8][8];
        zero8x8(acc);
        gemm8x8<128, 132>(sA, sB, tx, ty, acc);

        // write a ⊙ v back into sA
#pragma unroll
        for (int i = 0; i < 8; i++) {
            int r = ROW8(i);
            float a0 = sAf[r * 8 + (tx >> 2)];
            float a1 = sAf[r * 8 + 4 + (tx >> 2)];
            *(float4*)(sA + r * 132 + 4 * tx) =
                make_float4(acc[i][0] * a0, acc[i][1] * a0, acc[i][2] * a0, acc[i][3] * a0);
            *(float4*)(sA + r * 132 + 64 + 4 * tx) =
                make_float4(acc[i][4] * a1, acc[i][5] * a1, acc[i][6] * a1, acc[i][7] * a1);
        }
        __syncthreads();

        // segmented column reduction: thread = (16-row segment, 4-col group)
        {
            int colg = tid & 31, segr = tid >> 5;
            int r0 = segr * 16;
            float4 accv = make_float4(0.f, 0.f, 0.f, 0.f);
            int curd = sDst[r0];
#pragma unroll
            for (int r = r0; r < r0 + 16; r++) {
                int d = sDst[r];
                if (d != curd) {
                    if (curd >= 0)
                        red_add_v4(g_msg + (size_t)curd * 128 + colg * 4, accv.x, accv.y, accv.z, accv.w);
                    accv = make_float4(0.f, 0.f, 0.f, 0.f);
                    curd = d;
                }
                float4 vv = *(const float4*)(sA + r * 132 + colg * 4);
                accv.x += vv.x; accv.y += vv.y; accv.z += vv.z; accv.w += vv.w;
            }
            if (curd >= 0)
                red_add_v4(g_msg + (size_t)curd * 128 + colg * 4, accv.x, accv.y, accv.z, accv.w);
        }
        __syncthreads();
    }
}

// x += msg @ Wo
__global__ __launch_bounds__(256) void k_out(float* __restrict__ x,
                                             const float* __restrict__ Wo) {
    extern __shared__ float sm[];
    float* sA = sm;
    float* sB = sA + 128 * 132;
    int tid = threadIdx.x, tx = tid & 15, ty = tid >> 4;
    int n0 = blockIdx.x * 128;

    for (int i = tid; i < 128 * 128; i += 256) {
        int r = i >> 7, c = i & 127;
        int n = n0 + r;
        sA[r * 132 + c] = (n < NA) ? g_msg[n * 128 + c] : 0.f;
    }
    for (int i = tid; i < 128 * 128; i += 256) sB[i] = Wo[i];
    __syncthreads();

    float acc[8][8];
    zero8x8(acc);
    gemm8x8<128, 132>(sA, sB, tx, ty, acc);
#pragma unroll
    for (int i = 0; i < 8; i++) {
        int n = n0 + ROW8(i);
        if (n < NA) {
            float4 o0 = *(float4*)(x + n * 128 + 4 * tx);
            float4 o1 = *(float4*)(x + n * 128 + 64 + 4 * tx);
            o0.x += acc[i][0]; o0.y += acc[i][1]; o0.z += acc[i][2]; o0.w += acc[i][3];
            o1.x += acc[i][4]; o1.y += acc[i][5]; o1.z += acc[i][6]; o1.w += acc[i][7];
            *(float4*)(x + n * 128 + 4 * tx) = o0;
            *(float4*)(x + n * 128 + 64 + 4 * tx) = o1;
        }
    }
}

__global__ void k_reset() {
    int i = blockIdx.x * blockDim.x + threadIdx.x;
    if (i < NA * DD) g_msg[i] = 0.f;
    if (i < NA * HH) { g_den[i] = 0.f; g_smax[i] = 0u; }
}

// ---------------- launch ----------------
extern "C" void kernel_launch(void* const* d_in, const int* in_sizes, int n_in,
                              void* d_out, int out_size) {
    const float* xyz = (const float*)d_in[0];
    const float* emb = (const float*)d_in[1];
    const float* te  = (const float*)d_in[2];
    const float* Wl  = (const float*)d_in[3];
    const float* bl  = (const float*)d_in[4];
    const float* W1f = (const float*)d_in[5];
    const float* b1f = (const float*)d_in[6];
    const float* W2f = (const float*)d_in[7];
    const float* b2f = (const float*)d_in[8];
    const float* Wq  = (const float*)d_in[9];
    const float* Wk  = (const float*)d_in[10];
    const float* Wv  = (const float*)d_in[11];
    const float* Wo  = (const float*)d_in[12];
    const int*   z   = (const int*)d_in[13];
    const int*   src = (const int*)d_in[14];
    const int*   dst = (const int*)d_in[15];
    float* x = (float*)d_out;

    const int SM_FILTER = (128 * 36 + 128 * 132 + 2 * 32 * 128 + 128 * 128 + 4 * 128) * 4;
    const int SM_HQK    = (128 * 132 + 128 * 128) * 4;
    const int SM_MSGV   = (128 * 132 + 128 * 128 + 128 * 8 + 128) * 4;
    const int SM_OUT    = (128 * 132 + 128 * 128) * 4;

    cudaFuncSetAttribute(k_filter, cudaFuncAttributeMaxDynamicSharedMemorySize, SM_FILTER);
    cudaFuncSetAttribute(k_hqk,    cudaFuncAttributeMaxDynamicSharedMemorySize, SM_HQK);
    cudaFuncSetAttribute(k_msgv,   cudaFuncAttributeMaxDynamicSharedMemorySize, SM_MSGV);
    cudaFuncSetAttribute(k_out,    cudaFuncAttributeMaxDynamicSharedMemorySize, SM_OUT);

    k_embed<<<(NA * DD + 255) / 256, 256>>>(emb, z, x);
    k_hist<<<NE / 256, 256>>>(xyz, src, dst);
    k_scan<<<1, 512>>>();
    k_scatter<<<NE / 256, 256>>>(xyz, src, dst);
    k_filter<<<NSM, 256, SM_FILTER>>>(xyz, Wl, bl, W1f, b1f, W2f, b2f);

    const int NBLK = (NA + 127) / 128;   // 157
    for (int it = 0; it < NIT; it++) {
        k_reset<<<(NA * DD + 255) / 256, 256>>>();
        k_hqk<<<NBLK, 256, SM_HQK>>>(x, te, Wq, Wk, it);
        k_s<<<NE / 8, 256>>>();
        k_es<<<NE / 256, 256>>>();
        k_recip<<<(NA * HH + 255) / 256, 256>>>();
        k_msgv<<<NSM, 256, SM_MSGV>>>(Wv);
        k_out<<<NBLK, 256, SM_OUT>>>(x, Wo);
    }
}

// round 4
// speedup vs baseline: 1.5576x; 1.5576x over previous
#include <cuda_runtime.h>
#include <math.h>
#include <stdint.h>

#define NA 20000
#define NE 640000
#define DD 128
#define GG 32
#define HH 8
#define NIT 4
#define NSM 148

// ---------------- device scratch ----------------
__device__ float    g_Wfil[(size_t)NE * DD];
__device__ int      g_ssrc[NE];     // src, sorted by dst
__device__ int      g_sdst[NE];     // dst, sorted (nondecreasing)
__device__ int      g_lsrc[NE];     // live subset, sorted by dst
__device__ int      g_ldst[NE];
__device__ int      g_lpos[NE];     // live -> sorted-edge position
__device__ int      g_cnt_all[NA];
__device__ int      g_cnt_live[NA];
__device__ int      g_off_all[NA];
__device__ int      g_off_live[NA];
__device__ int      g_nlive;
__device__ float    g_h[NA * DD];
__device__ float    g_Q[NA * DD];
__device__ float    g_K[NA * DD];
__device__ float    g_s[NE * HH];
__device__ unsigned g_smax[NA * HH];
__device__ float    g_den[NA * HH];
__device__ float    g_msg[NA * DD];

__device__ __forceinline__ unsigned fenc(float f) {
    unsigned u = __float_as_uint(f);
    return (u & 0x80000000u) ? ~u : (u | 0x80000000u);
}
__device__ __forceinline__ float fdec(unsigned u) {
    return __uint_as_float((u & 0x80000000u) ? (u & 0x7fffffffu) : ~u);
}
__device__ __forceinline__ void red_add_v4(float* p, float x, float y, float z, float w) {
    asm volatile("red.global.add.v4.f32 [%0], {%1,%2,%3,%4};"
                 :: "l"(p), "f"(x), "f"(y), "f"(z), "f"(w) : "memory");
}
__device__ __forceinline__ float edge_r(const float* xyz, int s, int d) {
    float dx = xyz[3 * s]     - xyz[3 * d];
    float dy = xyz[3 * s + 1] - xyz[3 * d + 1];
    float dz = xyz[3 * s + 2] - xyz[3 * d + 2];
    return sqrtf(dx * dx + dy * dy + dz * dz + 1e-12f);
}

// ---------------- tf32 MMA core ----------------
__device__ __forceinline__ uint32_t f2tf(float f) {
    uint32_t u;
    asm("cvt.rna.tf32.f32 %0, %1;" : "=r"(u) : "f"(f));
    return u;
}
__device__ __forceinline__ float f2tff(float f) { return __uint_as_float(f2tf(f)); }

__device__ __forceinline__ void mma8(float4& d,
                                     uint32_t a0, uint32_t a1, uint32_t a2, uint32_t a3,
                                     uint32_t b0, uint32_t b1) {
    asm volatile(
        "mma.sync.aligned.m16n8k8.row.col.f32.tf32.tf32.f32 "
        "{%0,%1,%2,%3},{%4,%5,%6,%7},{%8,%9},{%0,%1,%2,%3};"
        : "+f"(d.x), "+f"(d.y), "+f"(d.z), "+f"(d.w)
        : "r"(a0), "r"(a1), "r"(a2), "r"(a3), "r"(b0), "r"(b1));
}
__device__ __forceinline__ void zacc(float4 acc[2][8]) {
#pragma unroll
    for (int i = 0; i < 2; i++)
#pragma unroll
        for (int j = 0; j < 8; j++) acc[i][j] = make_float4(0.f, 0.f, 0.f, 0.f);
}

// 128x128xK tile GEMM. 8 warps: wm = w&3 (32-row block), wn = w>>2 (64-col block).
// sA:  row-major [128][LDA] (tf32 bits as float)
// sBt: transposed [n=128][LDB] (tf32 bits as float)
template <int KSTEPS, int LDA, int LDB>
__device__ __forceinline__ void mma_tile(const float* __restrict__ sA,
                                         const float* __restrict__ sBt,
                                         int wm, int wn, int lane,
                                         float4 acc[2][8]) {
    int g = lane >> 2, t = lane & 3;
    const float* A0 = sA + (32 * wm + g) * LDA + t;
    const float* A1 = A0 + 16 * LDA;
    const float* Bb = sBt + (64 * wn + g) * LDB + t;
#pragma unroll
    for (int ks = 0; ks < KSTEPS; ks++) {
        const int k0 = ks * 8;
        uint32_t a00 = __float_as_uint(A0[k0]);
        uint32_t a01 = __float_as_uint(A0[8 * LDA + k0]);
        uint32_t a02 = __float_as_uint(A0[k0 + 4]);
        uint32_t a03 = __float_as_uint(A0[8 * LDA + k0 + 4]);
        uint32_t a10 = __float_as_uint(A1[k0]);
        uint32_t a11 = __float_as_uint(A1[8 * LDA + k0]);
        uint32_t a12 = __float_as_uint(A1[k0 + 4]);
        uint32_t a13 = __float_as_uint(A1[8 * LDA + k0 + 4]);
#pragma unroll
        for (int j = 0; j < 8; j++) {
            uint32_t b0 = __float_as_uint(Bb[(8 * j) * LDB + k0]);
            uint32_t b1 = __float_as_uint(Bb[(8 * j) * LDB + k0 + 4]);
            mma8(acc[0][j], a00, a01, a02, a03, b0, b1);
            mma8(acc[1][j], a10, a11, a12, a13, b0, b1);
        }
    }
}

// ---------------- setup ----------------
__global__ void k_embed(const float* __restrict__ emb, const int* __restrict__ z,
                        float* __restrict__ x) {
    int i = blockIdx.x * blockDim.x + threadIdx.x;
    if (i < NA) { g_cnt_all[i] = 0; g_cnt_live[i] = 0; }
    if (i < NA * DD) {
        int n = i >> 7, d = i & 127;
        x[i] = emb[z[n] * DD + d];
    }
}

__global__ void k_hist(const float* __restrict__ xyz, const int* __restrict__ src,
                       const int* __restrict__ dst) {
    int e = blockIdx.x * blockDim.x + threadIdx.x;
    if (e >= NE) return;
    int s = src[e], d = dst[e];
    atomicAdd(&g_cnt_all[d], 1);
    if (edge_r(xyz, s, d) < 8.f) atomicAdd(&g_cnt_live[d], 1);
}

__global__ __launch_bounds__(512) void k_scan() {
    __shared__ int part[512];
    __shared__ int total;
    int t = threadIdx.x;
    const int CH = (NA + 511) / 512;
#pragma unroll 1
    for (int pass = 0; pass < 2; pass++) {
        int* cnt = pass ? g_cnt_live : g_cnt_all;
        int* off = pass ? g_off_live : g_off_all;
        int lo = t * CH, hi = min(lo + CH, NA);
        int s = 0;
        for (int i = lo; i < hi; i++) s += cnt[i];
        part[t] = s;
        __syncthreads();
        if (t == 0) {
            int run = 0;
            for (int i = 0; i < 512; i++) { int v = part[i]; part[i] = run; run += v; }
            total = run;
        }
        __syncthreads();
        int run = part[t];
        for (int i = lo; i < hi; i++) { int v = cnt[i]; off[i] = run; run += v; cnt[i] = 0; }
        if (pass == 1 && t == 0) g_nlive = total;
        __syncthreads();
    }
}

__global__ void k_scatter(const float* __restrict__ xyz, const int* __restrict__ src,
                          const int* __restrict__ dst) {
    int e = blockIdx.x * blockDim.x + threadIdx.x;
    if (e >= NE) return;
    int s = src[e], d = dst[e];
    int pos = g_off_all[d] + atomicAdd(&g_cnt_all[d], 1);
    g_ssrc[pos] = s;
    g_sdst[pos] = d;
    if (edge_r(xyz, s, d) < 8.f) {
        int lp = g_off_live[d] + atomicAdd(&g_cnt_live[d], 1);
        g_lsrc[lp] = s; g_ldst[lp] = d; g_lpos[lp] = pos;
    }
}

// ---------------- filter (persistent, tf32 MMA) ----------------
__global__ __launch_bounds__(256) void k_filter(
    const float* __restrict__ xyz,
    const float* __restrict__ Wl, const float* __restrict__ bl,
    const float* __restrict__ W1f, const float* __restrict__ b1f,
    const float* __restrict__ W2f, const float* __restrict__ b2f) {
    extern __shared__ float sm[];
    float* sf   = sm;                    // 128*36
    float* sg   = sf + 128 * 36;         // 128*132
    float* sW1t = sg + 128 * 132;        // 128*36  (transposed, tf32)
    float* sWlt = sW1t + 128 * 36;       // 128*36
    float* sW2t = sWlt + 128 * 36;       // 128*132
    float* sr   = sW2t + 128 * 132;      // 128
    float* sC   = sr + 128;              // 128
    float* sb1  = sC + 128;              // 128
    float* sb   = sb1 + 128;             // 128

    int tid = threadIdx.x, lane = tid & 31, w = tid >> 5;
    int wm = w & 3, wn = w >> 2;
    int g = lane >> 2, t4 = lane & 3;

    for (int i = tid; i < 32 * 128; i += 256) {
        int k = i >> 7, n = i & 127;
        sW1t[n * 36 + k] = f2tff(W1f[i]);
        sWlt[n * 36 + k] = f2tff(Wl[i]);
    }
    for (int i = tid; i < 128 * 128; i += 256) {
        int k = i >> 7, n = i & 127;
        sW2t[n * 132 + k] = f2tff(W2f[i]);
    }
    if (tid < 128) { sb1[tid] = b1f[tid]; sb[tid] = bl[tid] + b2f[tid]; }

    int nlive = g_nlive;
    for (int tt = blockIdx.x; tt * 128 < nlive; tt += gridDim.x) {
        if (tid < 128) {
            int li = tt * 128 + tid;
            float r = 100.f, C = 0.f;
            if (li < nlive) {
                r = edge_r(xyz, g_lsrc[li], g_ldst[li]);
                C = (r < 8.f) ? (0.5f * (cospif(r * 0.125f) + 1.f)) : 0.f;
            }
            sr[tid] = r; sC[tid] = C;
        }
        __syncthreads();
        {
            int el = tid >> 1, kb = (tid & 1) * 16;
            float r = sr[el];
#pragma unroll
            for (int q = 0; q < 16; q++) {
                float off = (float)(kb + q) * (8.f / 31.f);
                float u = (r - off) * (31.f / 8.f);
                sf[el * 36 + kb + q] = f2tff(__expf(-0.5f * u * u));
            }
        }
        __syncthreads();

        float4 acc[2][8];
        zacc(acc);
        mma_tile<4, 36, 36>(sf, sW1t, wm, wn, lane, acc);
        __syncthreads();
        // sg = tf32(swish(acc + b1))
#pragma unroll
        for (int mi = 0; mi < 2; mi++) {
            int r = 32 * wm + 16 * mi + g;
#pragma unroll
            for (int j = 0; j < 8; j++) {
                int c = 64 * wn + 8 * j + 2 * t4;
                float4 d = acc[mi][j];
                float v0 = d.x + sb1[c], v1 = d.y + sb1[c + 1];
                float v2 = d.z + sb1[c], v3 = d.w + sb1[c + 1];
                sg[r * 132 + c]           = f2tff(v0 / (1.f + __expf(-v0)));
                sg[r * 132 + c + 1]       = f2tff(v1 / (1.f + __expf(-v1)));
                sg[(r + 8) * 132 + c]     = f2tff(v2 / (1.f + __expf(-v2)));
                sg[(r + 8) * 132 + c + 1] = f2tff(v3 / (1.f + __expf(-v3)));
            }
        }
        __syncthreads();

        zacc(acc);
        mma_tile<4, 36, 36>(sf, sWlt, wm, wn, lane, acc);
        mma_tile<16, 132, 132>(sg, sW2t, wm, wn, lane, acc);

#pragma unroll
        for (int mi = 0; mi < 2; mi++) {
            int r = 32 * wm + 16 * mi + g;
#pragma unroll
            for (int j = 0; j < 8; j++) {
                int c = 64 * wn + 8 * j + 2 * t4;
                float4 d = acc[mi][j];
                int li0 = tt * 128 + r, li1 = li0 + 8;
                if (li0 < nlive) {
                    float Cv = sC[r];
                    *(float2*)(g_Wfil + (size_t)li0 * 128 + c) =
                        make_float2((d.x + sb[c]) * Cv, (d.y + sb[c + 1]) * Cv);
                }
                if (li1 < nlive) {
                    float Cv = sC[r + 8];
                    *(float2*)(g_Wfil + (size_t)li1 * 128 + c) =
                        make_float2((d.z + sb[c]) * Cv, (d.w + sb[c + 1]) * Cv);
                }
            }
        }
        __syncthreads();
    }
}

// ---------------- h/Q/K (tf32 MMA) ----------------
__global__ __launch_bounds__(256) void k_hqk(const float* __restrict__ x,
                                             const float* __restrict__ te,
                                             const float* __restrict__ Wq,
                                             const float* __restrict__ Wk, int it) {
    extern __shared__ float sm[];
    float* sh  = sm;                // 128*132 (tf32)
    float* sBt = sh + 128 * 132;    // 128*132 (transposed, tf32)
    int tid = threadIdx.x, lane = tid & 31, w = tid >> 5;
    int wm = w & 3, wn = w >> 2;
    int g = lane >> 2, t4 = lane & 3;
    int n0 = blockIdx.x * 128;

    for (int i = tid; i < 128 * 128; i += 256) {
        int r = i >> 7, c = i & 127;
        int n = n0 + r;
        float v = 0.f;
        if (n < NA) {
            v = x[n * 128 + c] + te[it * 128 + c];
            g_h[n * 128 + c] = v;
        }
        sh[r * 132 + c] = f2tff(v);
    }
    for (int i = tid; i < 128 * 128; i += 256) {
        int k = i >> 7, n = i & 127;
        sBt[n * 132 + k] = f2tff(Wq[i]);
    }
    __syncthreads();

    float4 acc[2][8];
    zacc(acc);
    mma_tile<16, 132, 132>(sh, sBt, wm, wn, lane, acc);
#pragma unroll
    for (int mi = 0; mi < 2; mi++) {
        int r = 32 * wm + 16 * mi + g;
#pragma unroll
        for (int j = 0; j < 8; j++) {
            int c = 64 * wn + 8 * j + 2 * t4;
            float4 d = acc[mi][j];
            int n1 = n0 + r, n2 = n1 + 8;
            if (n1 < NA) *(float2*)(g_Q + n1 * 128 + c) = make_float2(d.x, d.y);
            if (n2 < NA) *(float2*)(g_Q + n2 * 128 + c) = make_float2(d.z, d.w);
        }
    }
    __syncthreads();
    for (int i = tid; i < 128 * 128; i += 256) {
        int k = i >> 7, n = i & 127;
        sBt[n * 132 + k] = f2tff(Wk[i]);
    }
    __syncthreads();
    zacc(acc);
    mma_tile<16, 132, 132>(sh, sBt, wm, wn, lane, acc);
#pragma unroll
    for (int mi = 0; mi < 2; mi++) {
        int r = 32 * wm + 16 * mi + g;
#pragma unroll
        for (int j = 0; j < 8; j++) {
            int c = 64 * wn + 8 * j + 2 * t4;
            float4 d = acc[mi][j];
            int n1 = n0 + r, n2 = n1 + 8;
            if (n1 < NA) *(float2*)(g_K + n1 * 128 + c) = make_float2(d.x, d.y);
            if (n2 < NA) *(float2*)(g_K + n2 * 128 + c) = make_float2(d.z, d.w);
        }
    }
}

// scores + segment max; one warp per edge
__global__ void k_s() {
    int w = (blockIdx.x * blockDim.x + threadIdx.x) >> 5;
    int lane = threadIdx.x & 31;
    if (w >= NE) return;
    int s = g_ssrc[w], d = g_sdst[w];
    float4 q = *(const float4*)(g_Q + d * 128 + lane * 4);
    float4 k = *(const float4*)(g_K + s * 128 + lane * 4);
    float p = q.x * k.x + q.y * k.y + q.z * k.z + q.w * k.w;
    p += __shfl_xor_sync(0xffffffffu, p, 1);
    p += __shfl_xor_sync(0xffffffffu, p, 2);
    if ((lane & 3) == 0) {
        int h = lane >> 2;
        float sv = p * 0.25f;
        g_s[w * 8 + h] = sv;
        atomicMax(&g_smax[d * 8 + h], fenc(sv));
    }
}

// es = exp(s - max); warp-segmented denom reduction
__global__ void k_es() {
    int e = blockIdx.x * blockDim.x + threadIdx.x;
    int lane = threadIdx.x & 31;
    int d = g_sdst[e];
    uint4 m0 = *(const uint4*)(g_smax + d * 8);
    uint4 m1 = *(const uint4*)(g_smax + d * 8 + 4);
    float4 s0 = *(const float4*)(g_s + e * 8);
    float4 s1 = *(const float4*)(g_s + e * 8 + 4);
    float v[8];
    v[0] = __expf(s0.x - fdec(m0.x)); v[1] = __expf(s0.y - fdec(m0.y));
    v[2] = __expf(s0.z - fdec(m0.z)); v[3] = __expf(s0.w - fdec(m0.w));
    v[4] = __expf(s1.x - fdec(m1.x)); v[5] = __expf(s1.y - fdec(m1.y));
    v[6] = __expf(s1.z - fdec(m1.z)); v[7] = __expf(s1.w - fdec(m1.w));
    *(float4*)(g_s + e * 8)     = make_float4(v[0], v[1], v[2], v[3]);
    *(float4*)(g_s + e * 8 + 4) = make_float4(v[4], v[5], v[6], v[7]);
#pragma unroll
    for (int delta = 1; delta < 32; delta <<= 1) {
        int od = __shfl_down_sync(0xffffffffu, d, delta);
        float ov[8];
#pragma unroll
        for (int q = 0; q < 8; q++) ov[q] = __shfl_down_sync(0xffffffffu, v[q], delta);
        if (lane + delta < 32 && od == d)
#pragma unroll
            for (int q = 0; q < 8; q++) v[q] += ov[q];
    }
    int pd = __shfl_up_sync(0xffffffffu, d, 1);
    if (lane == 0 || pd != d) {
        red_add_v4(g_den + d * 8,     v[0], v[1], v[2], v[3]);
        red_add_v4(g_den + d * 8 + 4, v[4], v[5], v[6], v[7]);
    }
}

__global__ void k_recip() {
    int i = blockIdx.x * blockDim.x + threadIdx.x;
    if (i < NA * HH) g_den[i] = 1.f / (g_den[i] + 1e-12f);
}

// ---------------- msgv (persistent, tf32 MMA + segmented reduce) ----------------
__global__ __launch_bounds__(256) void k_msgv(const float* __restrict__ Wv) {
    extern __shared__ float sm[];
    float* sA   = sm;                  // 128*132
    float* sBt  = sA + 128 * 132;      // 128*132 (Wv transposed, tf32)
    float* sAf  = sBt + 128 * 132;     // 128*8
    int*   sDst = (int*)(sAf + 128 * 8);
    int tid = threadIdx.x, lane = tid & 31, w = tid >> 5;
    int wm = w & 3, wn = w >> 2;
    int g = lane >> 2, t4 = lane & 3;

    for (int i = tid; i < 128 * 128; i += 256) {
        int k = i >> 7, n = i & 127;
        sBt[n * 132 + k] = f2tff(Wv[i]);
    }
    int nlive = g_nlive;

    for (int tt = blockIdx.x; tt * 128 < nlive; tt += gridDim.x) {
        if (tid < 128) {
            int li = tt * 128 + tid;
            if (li < nlive) {
                int d = g_ldst[li];
                int pos = g_lpos[li];
                sDst[tid] = d;
                float4 s0 = *(const float4*)(g_s + (size_t)pos * 8);
                float4 s1 = *(const float4*)(g_s + (size_t)pos * 8 + 4);
                float4 d0 = *(const float4*)(g_den + d * 8);
                float4 d1 = *(const float4*)(g_den + d * 8 + 4);
                *(float4*)(sAf + tid * 8)     = make_float4(s0.x * d0.x, s0.y * d0.y, s0.z * d0.z, s0.w * d0.w);
                *(float4*)(sAf + tid * 8 + 4) = make_float4(s1.x * d1.x, s1.y * d1.y, s1.z * d1.z, s1.w * d1.w);
            } else sDst[tid] = -1;
        }
        {
            int r = tid >> 1, cb = (tid & 1) * 64;
            int li = tt * 128 + r;
            if (li < nlive) {
                int s = g_lsrc[li];
                const float4* wf = (const float4*)(g_Wfil + (size_t)li * 128 + cb);
                const float4* hp = (const float4*)(g_h + (size_t)s * 128 + cb);
#pragma unroll
                for (int q = 0; q < 16; q++) {
                    float4 ww = wf[q], hh = hp[q];
                    *(float4*)(sA + r * 132 + cb + q * 4) =
                        make_float4(f2tff(ww.x * hh.x), f2tff(ww.y * hh.y),
                                    f2tff(ww.z * hh.z), f2tff(ww.w * hh.w));
                }
            } else {
#pragma unroll
                for (int q = 0; q < 16; q++)
                    *(float4*)(sA + r * 132 + cb + q * 4) = make_float4(0.f, 0.f, 0.f, 0.f);
            }
        }
        __syncthreads();

        float4 acc[2][8];
        zacc(acc);
        mma_tile<16, 132, 132>(sA, sBt, wm, wn, lane, acc);
        __syncthreads();   // all warps done reading sA before overwrite

        // write a ⊙ v back into sA
#pragma unroll
        for (int mi = 0; mi < 2; mi++) {
            int r = 32 * wm + 16 * mi + g;
#pragma unroll
            for (int j = 0; j < 8; j++) {
                int c = 64 * wn + 8 * j + 2 * t4;
                float4 d = acc[mi][j];
                float a0 = sAf[r * 8 + (c >> 4)];
                float a1 = sAf[(r + 8) * 8 + (c >> 4)];
                *(float2*)(sA + r * 132 + c)       = make_float2(d.x * a0, d.y * a0);
                *(float2*)(sA + (r + 8) * 132 + c) = make_float2(d.z * a1, d.w * a1);
            }
        }
        __syncthreads();

        // segmented column reduction: thread = (16-row segment, 4-col group)
        {
            int colg = tid & 31, segr = tid >> 5;
            int r0 = segr * 16;
            float4 accv = make_float4(0.f, 0.f, 0.f, 0.f);
            int curd = sDst[r0];
#pragma unroll
            for (int r = r0; r < r0 + 16; r++) {
                int d = sDst[r];
                if (d != curd) {
                    if (curd >= 0)
                        red_add_v4(g_msg + (size_t)curd * 128 + colg * 4, accv.x, accv.y, accv.z, accv.w);
                    accv = make_float4(0.f, 0.f, 0.f, 0.f);
                    curd = d;
                }
                float4 vv = *(const float4*)(sA + r * 132 + colg * 4);
                accv.x += vv.x; accv.y += vv.y; accv.z += vv.z; accv.w += vv.w;
            }
            if (curd >= 0)
                red_add_v4(g_msg + (size_t)curd * 128 + colg * 4, accv.x, accv.y, accv.z, accv.w);
        }
        __syncthreads();
    }
}

// x += msg @ Wo  (tf32 MMA)
__global__ __launch_bounds__(256) void k_out(float* __restrict__ x,
                                             const float* __restrict__ Wo) {
    extern __shared__ float sm[];
    float* sA  = sm;
    float* sBt = sA + 128 * 132;
    int tid = threadIdx.x, lane = tid & 31, w = tid >> 5;
    int wm = w & 3, wn = w >> 2;
    int g = lane >> 2, t4 = lane & 3;
    int n0 = blockIdx.x * 128;

    for (int i = tid; i < 128 * 128; i += 256) {
        int r = i >> 7, c = i & 127;
        int n = n0 + r;
        sA[r * 132 + c] = (n < NA) ? f2tff(g_msg[n * 128 + c]) : 0.f;
    }
    for (int i = tid; i < 128 * 128; i += 256) {
        int k = i >> 7, n = i & 127;
        sBt[n * 132 + k] = f2tff(Wo[i]);
    }
    __syncthreads();

    float4 acc[2][8];
    zacc(acc);
    mma_tile<16, 132, 132>(sA, sBt, wm, wn, lane, acc);
#pragma unroll
    for (int mi = 0; mi < 2; mi++) {
        int r = 32 * wm + 16 * mi + g;
#pragma unroll
        for (int j = 0; j < 8; j++) {
            int c = 64 * wn + 8 * j + 2 * t4;
            float4 d = acc[mi][j];
            int n1 = n0 + r, n2 = n1 + 8;
            if (n1 < NA) {
                float2 o = *(float2*)(x + n1 * 128 + c);
                o.x += d.x; o.y += d.y;
                *(float2*)(x + n1 * 128 + c) = o;
            }
            if (n2 < NA) {
                float2 o = *(float2*)(x + n2 * 128 + c);
                o.x += d.z; o.y += d.w;
                *(float2*)(x + n2 * 128 + c) = o;
            }
        }
    }
}

__global__ void k_reset() {
    int i = blockIdx.x * blockDim.x + threadIdx.x;
    if (i < NA * DD) g_msg[i] = 0.f;
    if (i < NA * HH) { g_den[i] = 0.f; g_smax[i] = 0u; }
}

// ---------------- launch ----------------
extern "C" void kernel_launch(void* const* d_in, const int* in_sizes, int n_in,
                              void* d_out, int out_size) {
    const float* xyz = (const float*)d_in[0];
    const float* emb = (const float*)d_in[1];
    const float* te  = (const float*)d_in[2];
    const float* Wl  = (const float*)d_in[3];
    const float* bl  = (const float*)d_in[4];
    const float* W1f = (const float*)d_in[5];
    const float* b1f = (const float*)d_in[6];
    const float* W2f = (const float*)d_in[7];
    const float* b2f = (const float*)d_in[8];
    const float* Wq  = (const float*)d_in[9];
    const float* Wk  = (const float*)d_in[10];
    const float* Wv  = (const float*)d_in[11];
    const float* Wo  = (const float*)d_in[12];
    const int*   z   = (const int*)d_in[13];
    const int*   src = (const int*)d_in[14];
    const int*   dst = (const int*)d_in[15];
    float* x = (float*)d_out;

    const int SM_FILTER = (128 * 36 + 128 * 132 + 2 * 128 * 36 + 128 * 132 + 4 * 128) * 4;
    const int SM_HQK    = (2 * 128 * 132) * 4;
    const int SM_MSGV   = (2 * 128 * 132 + 128 * 8 + 128) * 4;
    const int SM_OUT    = (2 * 128 * 132) * 4;

    cudaFuncSetAttribute(k_filter, cudaFuncAttributeMaxDynamicSharedMemorySize, SM_FILTER);
    cudaFuncSetAttribute(k_hqk,    cudaFuncAttributeMaxDynamicSharedMemorySize, SM_HQK);
    cudaFuncSetAttribute(k_msgv,   cudaFuncAttributeMaxDynamicSharedMemorySize, SM_MSGV);
    cudaFuncSetAttribute(k_out,    cudaFuncAttributeMaxDynamicSharedMemorySize, SM_OUT);

    k_embed<<<(NA * DD + 255) / 256, 256>>>(emb, z, x);
    k_hist<<<NE / 256, 256>>>(xyz, src, dst);
    k_scan<<<1, 512>>>();
    k_scatter<<<NE / 256, 256>>>(xyz, src, dst);
    k_filter<<<NSM, 256, SM_FILTER>>>(xyz, Wl, bl, W1f, b1f, W2f, b2f);

    const int NBLK = (NA + 127) / 128;   // 157
    for (int it = 0; it < NIT; it++) {
        k_reset<<<(NA * DD + 255) / 256, 256>>>();
        k_hqk<<<NBLK, 256, SM_HQK>>>(x, te, Wq, Wk, it);
        k_s<<<NE / 8, 256>>>();
        k_es<<<NE / 256, 256>>>();
        k_recip<<<(NA * HH + 255) / 256, 256>>>();
        k_msgv<<<NSM, 256, SM_MSGV>>>(Wv);
        k_out<<<NBLK, 256, SM_OUT>>>(x, Wo);
    }
}